// round 2
// baseline (speedup 1.0000x reference)
#include <cuda_runtime.h>
#include <math.h>

#define RES   160
#define R3    (RES*RES*RES)
#define NRAY  2048
#define NS    558
#define NEARC 0.05f
#define FARC  3.5f
#define BGC   1.0f
#define STEPW 0.00625f                 /* STEPSIZE * VOXEL = 0.5 * 0.0125 */
#define ACT_SHIFT -4.5951198501345898f /* log(1/(1-0.01)-1) */

// ---- device scratch (static; no allocations allowed) ----
__device__ float  g_grid_t[(size_t)R3 * 12];   // channel-last grid, 196.6 MB
__device__ float4 g_scratch[NRAY * NS];        // {alpha, r, g, b} per sample
__device__ float  g_rayinfo[NRAY * 4];         // tmin, |d|, mask, pad
__device__ float  g_dbias[NRAY * 16];          // per-ray dir-layer1 bias (emb folded)

// =====================================================================
// Kernel 0: transpose grid (C,R,R,R) -> (R,R,R,C) channel-last
// =====================================================================
__global__ void k_transpose(const float* __restrict__ g) {
    int v = blockIdx.x * blockDim.x + threadIdx.x;
    if (v >= R3) return;
    float a[12];
#pragma unroll
    for (int c = 0; c < 12; c++) a[c] = __ldg(g + (size_t)c * R3 + v);
    float4* dst = reinterpret_cast<float4*>(g_grid_t + (size_t)v * 12);
    dst[0] = make_float4(a[0], a[1], a[2], a[3]);
    dst[1] = make_float4(a[4], a[5], a[6], a[7]);
    dst[2] = make_float4(a[8], a[9], a[10], a[11]);
}

// =====================================================================
// Kernel 1: per-ray precompute (tmin, |d|, mask, dir-layer1 bias)
// =====================================================================
__global__ void k_raypre(const float* __restrict__ ro, const float* __restrict__ rd,
                         const float* __restrict__ vd, const float* __restrict__ dw1,
                         const float* __restrict__ db1) {
    int r = blockIdx.x * blockDim.x + threadIdx.x;
    if (r >= NRAY) return;
    float ox = ro[3*r], oy = ro[3*r+1], oz = ro[3*r+2];
    float dx = rd[3*r], dy = rd[3*r+1], dz = rd[3*r+2];
    float vx = (dx == 0.f) ? 1e-6f : dx;
    float vy = (dy == 0.f) ? 1e-6f : dy;
    float vz = (dz == 0.f) ? 1e-6f : dz;
    float rax = (1.f - ox) / vx, rbx = (-1.f - ox) / vx;
    float ray_ = (1.f - oy) / vy, rby = (-1.f - oy) / vy;
    float raz = (1.f - oz) / vz, rbz = (-1.f - oz) / vz;
    float tmn = fmaxf(fmaxf(fminf(rax, rbx), fminf(ray_, rby)), fminf(raz, rbz));
    float tmx = fminf(fminf(fmaxf(rax, rbx), fmaxf(ray_, rby)), fmaxf(raz, rbz));
    tmn = fminf(fmaxf(tmn, NEARC), FARC);
    tmx = fminf(fmaxf(tmx, NEARC), FARC);
    float mask = (tmx <= tmn) ? 1.f : 0.f;
    float nn = sqrtf(dx*dx + dy*dy + dz*dz);
    g_rayinfo[4*r+0] = tmn;
    g_rayinfo[4*r+1] = nn;
    g_rayinfo[4*r+2] = mask;
    g_rayinfo[4*r+3] = 0.f;

    // positional encoding of viewdir (per-ray constant) folded into dir bias
    float wx = vd[3*r], wy = vd[3*r+1], wz = vd[3*r+2];
    float emb[39];
    emb[0] = wx; emb[1] = wy; emb[2] = wz;
    float f = 1.f;
#pragma unroll
    for (int l = 0; l < 6; l++) {
        emb[3+6*l+0] = sinf(wx*f); emb[3+6*l+1] = sinf(wy*f); emb[3+6*l+2] = sinf(wz*f);
        emb[3+6*l+3] = cosf(wx*f); emb[3+6*l+4] = cosf(wy*f); emb[3+6*l+5] = cosf(wz*f);
        f *= 2.f;
    }
#pragma unroll
    for (int j = 0; j < 16; j++) {
        float acc = db1[j];
#pragma unroll
        for (int k = 0; k < 39; k++) acc += emb[k] * dw1[(15+k)*16 + j];
        g_dbias[16*r + j] = acc;
    }
}

// =====================================================================
// Kernel 2: per-sample MLP evaluation -> scratch {alpha, rgb}
// grid: (ceil(NS/256), NRAY); one block serves one ray's sample chunk
// =====================================================================
// shared weight offsets (floats)
#define O_AW1 0
#define O_AB1 480
#define O_AW2 512
#define O_AB2 1536
#define O_AW3 1568
#define O_AB3 1696
#define O_PW1 1700
#define O_PB1 1892
#define O_PW2 1908
#define O_PB2 2164
#define O_PW3 2180
#define O_PB3 2436
#define O_DW1 2452
#define O_DW2 2692
#define O_DB2 2948
#define O_DW3 2964
#define O_DB3 3220
#define O_DW4 3236
#define O_DB4 3284
#define SW_TOT 3288

__global__ __launch_bounds__(256) void k_phaseA(
    const float* __restrict__ ro, const float* __restrict__ rd,
    const float* __restrict__ aw1, const float* __restrict__ ab1,
    const float* __restrict__ aw2, const float* __restrict__ ab2,
    const float* __restrict__ aw3, const float* __restrict__ ab3,
    const float* __restrict__ pw1, const float* __restrict__ pb1,
    const float* __restrict__ pw2, const float* __restrict__ pb2,
    const float* __restrict__ pw3, const float* __restrict__ pb3,
    const float* __restrict__ dw1,
    const float* __restrict__ dw2, const float* __restrict__ db2,
    const float* __restrict__ dw3, const float* __restrict__ db3,
    const float* __restrict__ dw4, const float* __restrict__ db4)
{
    __shared__ float sw[SW_TOT];
    __shared__ float s_db[16];
    __shared__ float s_ray[9];   // tmin, |d|, mask, ox,oy,oz, dx,dy,dz
    {
        int t = threadIdx.x;
        for (int i = t; i < 480;  i += 256) sw[O_AW1 + i] = aw1[i];
        for (int i = t; i < 32;   i += 256) sw[O_AB1 + i] = ab1[i];
        for (int i = t; i < 1024; i += 256) sw[O_AW2 + i] = aw2[i];
        for (int i = t; i < 32;   i += 256) sw[O_AB2 + i] = ab2[i];
        for (int i = t; i < 128;  i += 256) sw[O_AW3 + i] = aw3[i];
        for (int i = t; i < 4;    i += 256) sw[O_AB3 + i] = ab3[i];
        for (int i = t; i < 192;  i += 256) sw[O_PW1 + i] = pw1[i];
        for (int i = t; i < 16;   i += 256) sw[O_PB1 + i] = pb1[i];
        for (int i = t; i < 256;  i += 256) sw[O_PW2 + i] = pw2[i];
        for (int i = t; i < 16;   i += 256) sw[O_PB2 + i] = pb2[i];
        for (int i = t; i < 256;  i += 256) sw[O_PW3 + i] = pw3[i];
        for (int i = t; i < 16;   i += 256) sw[O_PB3 + i] = pb3[i];
        for (int i = t; i < 240;  i += 256) sw[O_DW1 + i] = dw1[i];  // rows 0..14 only
        for (int i = t; i < 256;  i += 256) sw[O_DW2 + i] = dw2[i];
        for (int i = t; i < 16;   i += 256) sw[O_DB2 + i] = db2[i];
        for (int i = t; i < 256;  i += 256) sw[O_DW3 + i] = dw3[i];
        for (int i = t; i < 16;   i += 256) sw[O_DB3 + i] = db3[i];
        for (int i = t; i < 48;   i += 256) sw[O_DW4 + i] = dw4[i];
        for (int i = t; i < 3;    i += 256) sw[O_DB4 + i] = db4[i];
        int ray0 = blockIdx.y;
        if (t < 16) s_db[t] = g_dbias[16*ray0 + t];
        if (t < 3)  s_ray[t] = g_rayinfo[4*ray0 + t];
        if (t >= 3 && t < 6) s_ray[t] = ro[3*ray0 + (t-3)];
        if (t >= 6 && t < 9) s_ray[t] = rd[3*ray0 + (t-6)];
    }
    __syncthreads();

    int ray = blockIdx.y;
    int s = blockIdx.x * 256 + threadIdx.x;
    if (s >= NS) return;
    int oi = ray * NS + s;

    float tmn = s_ray[0], rn = s_ray[1], mask = s_ray[2];
    float it = tmn + STEPW * (float)s / rn;
    float px = s_ray[3] + s_ray[6] * it;
    float py = s_ray[4] + s_ray[7] * it;
    float pz = s_ray[5] + s_ray[8] * it;
    bool inb = (mask == 0.f) &&
               px >= -1.f && px <= 1.f &&
               py >= -1.f && py <= 1.f &&
               pz >= -1.f && pz <= 1.f;
    if (!inb) { g_scratch[oi] = make_float4(0.f, 0.f, 0.f, 0.f); return; }

    // ---- trilinear from channel-last grid ----
    float gx = (px + 1.f) * 0.5f * 159.f;
    float gy = (py + 1.f) * 0.5f * 159.f;
    float gz = (pz + 1.f) * 0.5f * 159.f;
    float fx0 = floorf(gx), fy0 = floorf(gy), fz0 = floorf(gz);
    float wx1 = gx - fx0, wy1 = gy - fy0, wz1 = gz - fz0;
    float wx0 = 1.f - wx1, wy0 = 1.f - wy1, wz0 = 1.f - wz1;
    int ix0 = min(max((int)fx0, 0), 159); int ix1 = min(ix0 + 1, 159);
    int iy0 = min(max((int)fy0, 0), 159); int iy1 = min(iy0 + 1, 159);
    int iz0 = min(max((int)fz0, 0), 159); int iz1 = min(iz0 + 1, 159);

    float lat[12];
#pragma unroll
    for (int k = 0; k < 12; k++) lat[k] = 0.f;

#define ADD_CORNER(X, Y, Z, W) {                                                     \
        const float4* gp = reinterpret_cast<const float4*>(                          \
            g_grid_t + (size_t)((((X)*160 + (Y))*160) + (Z)) * 12);                  \
        float4 A = __ldg(gp), B = __ldg(gp+1), C = __ldg(gp+2);                      \
        float W_ = (W);                                                              \
        lat[0] += W_*A.x; lat[1] += W_*A.y; lat[2]  += W_*A.z; lat[3]  += W_*A.w;    \
        lat[4] += W_*B.x; lat[5] += W_*B.y; lat[6]  += W_*B.z; lat[7]  += W_*B.w;    \
        lat[8] += W_*C.x; lat[9] += W_*C.y; lat[10] += W_*C.z; lat[11] += W_*C.w; }

    ADD_CORNER(ix0, iy0, iz0, wx0*wy0*wz0);
    ADD_CORNER(ix0, iy0, iz1, wx0*wy0*wz1);
    ADD_CORNER(ix0, iy1, iz0, wx0*wy1*wz0);
    ADD_CORNER(ix0, iy1, iz1, wx0*wy1*wz1);
    ADD_CORNER(ix1, iy0, iz0, wx1*wy0*wz0);
    ADD_CORNER(ix1, iy0, iz1, wx1*wy0*wz1);
    ADD_CORNER(ix1, iy1, iz0, wx1*wy1*wz0);
    ADD_CORNER(ix1, iy1, iz1, wx1*wy1*wz1);
#undef ADD_CORNER

    // ---- attention MLP: [pz,py,px, lat] (15) -> 32 -> 32 -> 4 -> softmax[1] ----
    float xin[15];
    xin[0] = pz; xin[1] = py; xin[2] = px;
#pragma unroll
    for (int k = 0; k < 12; k++) xin[3+k] = lat[k];

    float h1[32];
#pragma unroll
    for (int j = 0; j < 32; j++) h1[j] = sw[O_AB1 + j];
#pragma unroll
    for (int i = 0; i < 15; i++) {
        float xi = xin[i];
#pragma unroll
        for (int j4 = 0; j4 < 8; j4++) {
            float4 w = *reinterpret_cast<const float4*>(&sw[O_AW1 + i*32 + j4*4]);
            h1[j4*4+0] += xi*w.x; h1[j4*4+1] += xi*w.y;
            h1[j4*4+2] += xi*w.z; h1[j4*4+3] += xi*w.w;
        }
    }
#pragma unroll
    for (int j = 0; j < 32; j++) h1[j] = fmaxf(h1[j], 0.f);

    float h2[32];
#pragma unroll
    for (int j = 0; j < 32; j++) h2[j] = sw[O_AB2 + j];
#pragma unroll
    for (int i = 0; i < 32; i++) {
        float xi = h1[i];
#pragma unroll
        for (int j4 = 0; j4 < 8; j4++) {
            float4 w = *reinterpret_cast<const float4*>(&sw[O_AW2 + i*32 + j4*4]);
            h2[j4*4+0] += xi*w.x; h2[j4*4+1] += xi*w.y;
            h2[j4*4+2] += xi*w.z; h2[j4*4+3] += xi*w.w;
        }
    }
#pragma unroll
    for (int j = 0; j < 32; j++) h2[j] = fmaxf(h2[j], 0.f);

    float o0 = sw[O_AB3+0], o1 = sw[O_AB3+1], o2 = sw[O_AB3+2], o3 = sw[O_AB3+3];
#pragma unroll
    for (int i = 0; i < 32; i++) {
        float4 w = *reinterpret_cast<const float4*>(&sw[O_AW3 + i*4]);
        float xi = h2[i];
        o0 += xi*w.x; o1 += xi*w.y; o2 += xi*w.z; o3 += xi*w.w;
    }
    float mx = fmaxf(fmaxf(o0, o1), fmaxf(o2, o3));
    float e0 = expf(o0-mx), e1 = expf(o1-mx), e2 = expf(o2-mx), e3 = expf(o3-mx);
    float att1 = e1 / (e0 + e1 + e2 + e3);

    // ---- pos MLP: lat (12) -> 16 -> 16 -> 16 ----
    float p1[16];
#pragma unroll
    for (int j = 0; j < 16; j++) p1[j] = sw[O_PB1 + j];
#pragma unroll
    for (int i = 0; i < 12; i++) {
        float xi = lat[i];
#pragma unroll
        for (int j4 = 0; j4 < 4; j4++) {
            float4 w = *reinterpret_cast<const float4*>(&sw[O_PW1 + i*16 + j4*4]);
            p1[j4*4+0] += xi*w.x; p1[j4*4+1] += xi*w.y;
            p1[j4*4+2] += xi*w.z; p1[j4*4+3] += xi*w.w;
        }
    }
#pragma unroll
    for (int j = 0; j < 16; j++) p1[j] = fmaxf(p1[j], 0.f);

    float p2[16];
#pragma unroll
    for (int j = 0; j < 16; j++) p2[j] = sw[O_PB2 + j];
#pragma unroll
    for (int i = 0; i < 16; i++) {
        float xi = p1[i];
#pragma unroll
        for (int j4 = 0; j4 < 4; j4++) {
            float4 w = *reinterpret_cast<const float4*>(&sw[O_PW2 + i*16 + j4*4]);
            p2[j4*4+0] += xi*w.x; p2[j4*4+1] += xi*w.y;
            p2[j4*4+2] += xi*w.z; p2[j4*4+3] += xi*w.w;
        }
    }
#pragma unroll
    for (int j = 0; j < 16; j++) p2[j] = fmaxf(p2[j], 0.f);

    float p3[16];
#pragma unroll
    for (int j = 0; j < 16; j++) p3[j] = sw[O_PB3 + j];
#pragma unroll
    for (int i = 0; i < 16; i++) {
        float xi = p2[i];
#pragma unroll
        for (int j4 = 0; j4 < 4; j4++) {
            float4 w = *reinterpret_cast<const float4*>(&sw[O_PW3 + i*16 + j4*4]);
            p3[j4*4+0] += xi*w.x; p3[j4*4+1] += xi*w.y;
            p3[j4*4+2] += xi*w.z; p3[j4*4+3] += xi*w.w;
        }
    }

    // ---- dir MLP: [p3[1:16] ; emb(folded bias)] -> 16 -> 16 -> 16 -> 3 ----
    float d1[16];
#pragma unroll
    for (int j = 0; j < 16; j++) d1[j] = s_db[j];
#pragma unroll
    for (int i = 0; i < 15; i++) {
        float xi = p3[i+1];
#pragma unroll
        for (int j4 = 0; j4 < 4; j4++) {
            float4 w = *reinterpret_cast<const float4*>(&sw[O_DW1 + i*16 + j4*4]);
            d1[j4*4+0] += xi*w.x; d1[j4*4+1] += xi*w.y;
            d1[j4*4+2] += xi*w.z; d1[j4*4+3] += xi*w.w;
        }
    }
#pragma unroll
    for (int j = 0; j < 16; j++) d1[j] = fmaxf(d1[j], 0.f);

    float d2[16];
#pragma unroll
    for (int j = 0; j < 16; j++) d2[j] = sw[O_DB2 + j];
#pragma unroll
    for (int i = 0; i < 16; i++) {
        float xi = d1[i];
#pragma unroll
        for (int j4 = 0; j4 < 4; j4++) {
            float4 w = *reinterpret_cast<const float4*>(&sw[O_DW2 + i*16 + j4*4]);
            d2[j4*4+0] += xi*w.x; d2[j4*4+1] += xi*w.y;
            d2[j4*4+2] += xi*w.z; d2[j4*4+3] += xi*w.w;
        }
    }
#pragma unroll
    for (int j = 0; j < 16; j++) d2[j] = fmaxf(d2[j], 0.f);

    float d3[16];
#pragma unroll
    for (int j = 0; j < 16; j++) d3[j] = sw[O_DB3 + j];
#pragma unroll
    for (int i = 0; i < 16; i++) {
        float xi = d2[i];
#pragma unroll
        for (int j4 = 0; j4 < 4; j4++) {
            float4 w = *reinterpret_cast<const float4*>(&sw[O_DW3 + i*16 + j4*4]);
            d3[j4*4+0] += xi*w.x; d3[j4*4+1] += xi*w.y;
            d3[j4*4+2] += xi*w.z; d3[j4*4+3] += xi*w.w;
        }
    }
#pragma unroll
    for (int j = 0; j < 16; j++) d3[j] = fmaxf(d3[j], 0.f);

    float r0 = sw[O_DB4+0], r1 = sw[O_DB4+1], r2 = sw[O_DB4+2];
#pragma unroll
    for (int i = 0; i < 16; i++) {
        float xi = d3[i];
        r0 += xi * sw[O_DW4 + i*3 + 0];
        r1 += xi * sw[O_DW4 + i*3 + 1];
        r2 += xi * sw[O_DW4 + i*3 + 2];
    }

    // ---- activations ----
    float dens = att1 * p3[0];
    float xs = dens + ACT_SHIFT;
    float sp = fmaxf(xs, 0.f) + log1pf(expf(-fabsf(xs)));   // softplus
    float alpha = 1.f - expf(-sp * 0.5f);
    float c0 = 1.f / (1.f + expf(-att1 * r0));
    float c1 = 1.f / (1.f + expf(-att1 * r1));
    float c2 = 1.f / (1.f + expf(-att1 * r2));

    g_scratch[oi] = make_float4(alpha, c0, c1, c2);
}

// =====================================================================
// Kernel 3: warp-per-ray alpha compositing (shfl prefix-product scan)
// =====================================================================
__global__ __launch_bounds__(256) void k_phaseB(float* __restrict__ out) {
    int gid  = blockIdx.x * blockDim.x + threadIdx.x;
    int ray  = gid >> 5;
    int lane = gid & 31;
    if (ray >= NRAY) return;

    float tmn = g_rayinfo[4*ray], rn = g_rayinfo[4*ray+1];
    float base_depth = tmn * rn;

    float T = 1.f;
    float sr = 0.f, sg = 0.f, sb = 0.f, sd = 0.f, sa = 0.f;

    for (int c0 = 0; c0 < NS; c0 += 32) {
        int s = c0 + lane;
        float4 rec = make_float4(0.f, 0.f, 0.f, 0.f);
        if (s < NS) rec = g_scratch[ray*NS + s];
        float a = rec.x;
        float q = fmaxf(1.f - a, 1e-10f);
        float ip = q;
#pragma unroll
        for (int off = 1; off < 32; off <<= 1) {
            float v = __shfl_up_sync(0xFFFFFFFFu, ip, off);
            if (lane >= off) ip *= v;
        }
        float ep = __shfl_up_sync(0xFFFFFFFFu, ip, 1);
        if (lane == 0) ep = 1.f;
        float w = a * T * ep;
        sr += w * rec.y;
        sg += w * rec.z;
        sb += w * rec.w;
        sd += w * (base_depth + STEPW * (float)s);
        sa += w;
        T *= __shfl_sync(0xFFFFFFFFu, ip, 31);
    }

#pragma unroll
    for (int off = 16; off > 0; off >>= 1) {
        sr += __shfl_xor_sync(0xFFFFFFFFu, sr, off);
        sg += __shfl_xor_sync(0xFFFFFFFFu, sg, off);
        sb += __shfl_xor_sync(0xFFFFFFFFu, sb, off);
        sd += __shfl_xor_sync(0xFFFFFFFFu, sd, off);
        sa += __shfl_xor_sync(0xFFFFFFFFu, sa, off);
    }

    if (lane == 0) {
        float depth = sd + T * FARC;
        out[ray*6+0] = sr + T * BGC;
        out[ray*6+1] = sg + T * BGC;
        out[ray*6+2] = sb + T * BGC;
        out[ray*6+3] = depth;
        out[ray*6+4] = 1.f / depth;
        out[ray*6+5] = sa;
    }
}

// =====================================================================
extern "C" void kernel_launch(void* const* d_in, const int* in_sizes, int n_in,
                              void* d_out, int out_size) {
    const float* ro  = (const float*)d_in[0];
    const float* rd  = (const float*)d_in[1];
    const float* vd  = (const float*)d_in[2];
    const float* grd = (const float*)d_in[3];
    const float* aw1 = (const float*)d_in[4];
    const float* ab1 = (const float*)d_in[5];
    const float* aw2 = (const float*)d_in[6];
    const float* ab2 = (const float*)d_in[7];
    const float* aw3 = (const float*)d_in[8];
    const float* ab3 = (const float*)d_in[9];
    const float* pw1 = (const float*)d_in[10];
    const float* pb1 = (const float*)d_in[11];
    const float* pw2 = (const float*)d_in[12];
    const float* pb2 = (const float*)d_in[13];
    const float* pw3 = (const float*)d_in[14];
    const float* pb3 = (const float*)d_in[15];
    const float* dw1 = (const float*)d_in[16];
    const float* db1 = (const float*)d_in[17];
    const float* dw2 = (const float*)d_in[18];
    const float* db2 = (const float*)d_in[19];
    const float* dw3 = (const float*)d_in[20];
    const float* db3 = (const float*)d_in[21];
    const float* dw4 = (const float*)d_in[22];
    const float* db4 = (const float*)d_in[23];

    k_transpose<<<(R3 + 255) / 256, 256>>>(grd);
    k_raypre<<<(NRAY + 255) / 256, 256>>>(ro, rd, vd, dw1, db1);
    dim3 gA((NS + 255) / 256, NRAY);
    k_phaseA<<<gA, 256>>>(ro, rd,
                          aw1, ab1, aw2, ab2, aw3, ab3,
                          pw1, pb1, pw2, pb2, pw3, pb3,
                          dw1, dw2, db2, dw3, db3, dw4, db4);
    k_phaseB<<<(NRAY * 32) / 256, 256>>>((float*)d_out);
}

// round 3
// speedup vs baseline: 1.1299x; 1.1299x over previous
#include <cuda_runtime.h>
#include <math.h>

#define RES   160
#define R3    (RES*RES*RES)
#define NRAY  2048
#define NS    558
#define NEARC 0.05f
#define FARC  3.5f
#define BGC   1.0f
#define STEPW 0.00625f                 /* STEPSIZE * VOXEL = 0.5 * 0.0125 */
#define ACT_SHIFT -4.5951198501345898f /* log(1/(1-0.01)-1) */

typedef unsigned long long u64;

// ---- packed f32x2 helpers (Blackwell-only; ptxas never auto-fuses FFMA2) ----
__device__ __forceinline__ u64 pk2(float lo, float hi) {
    u64 r; asm("mov.b64 %0, {%1, %2};" : "=l"(r) : "f"(lo), "f"(hi)); return r;
}
__device__ __forceinline__ void upk2(u64 v, float& lo, float& hi) {
    asm("mov.b64 {%0, %1}, %2;" : "=f"(lo), "=f"(hi) : "l"(v));
}
__device__ __forceinline__ void fma2(u64& d, u64 a, u64 b) {
    asm("fma.rn.f32x2 %0, %1, %2, %0;" : "+l"(d) : "l"(a), "l"(b));
}

// ---- device scratch (static; no allocations allowed) ----
__device__ float  g_grid_t[(size_t)R3 * 12];   // channel-last grid, 196.6 MB
__device__ float4 g_scratch[NRAY * NS];        // {alpha, r, g, b} per sample
__device__ float  g_rayinfo[NRAY * 4];         // tmin, |d|, mask, pad
__device__ float  g_dbias[NRAY * 16];          // per-ray dir-layer1 bias (emb folded)

// =====================================================================
// Kernel 0: transpose grid (C,R,R,R) -> (R,R,R,C) channel-last
// =====================================================================
__global__ void k_transpose(const float* __restrict__ g) {
    int v = blockIdx.x * blockDim.x + threadIdx.x;
    if (v >= R3) return;
    float a[12];
#pragma unroll
    for (int c = 0; c < 12; c++) a[c] = __ldg(g + (size_t)c * R3 + v);
    float4* dst = reinterpret_cast<float4*>(g_grid_t + (size_t)v * 12);
    dst[0] = make_float4(a[0], a[1], a[2], a[3]);
    dst[1] = make_float4(a[4], a[5], a[6], a[7]);
    dst[2] = make_float4(a[8], a[9], a[10], a[11]);
}

// =====================================================================
// Kernel 1: per-ray precompute (tmin, |d|, mask, dir-layer1 bias)
// =====================================================================
__global__ void k_raypre(const float* __restrict__ ro, const float* __restrict__ rd,
                         const float* __restrict__ vd, const float* __restrict__ dw1,
                         const float* __restrict__ db1) {
    int r = blockIdx.x * blockDim.x + threadIdx.x;
    if (r >= NRAY) return;
    float ox = ro[3*r], oy = ro[3*r+1], oz = ro[3*r+2];
    float dx = rd[3*r], dy = rd[3*r+1], dz = rd[3*r+2];
    float vx = (dx == 0.f) ? 1e-6f : dx;
    float vy = (dy == 0.f) ? 1e-6f : dy;
    float vz = (dz == 0.f) ? 1e-6f : dz;
    float rax = (1.f - ox) / vx, rbx = (-1.f - ox) / vx;
    float ray_ = (1.f - oy) / vy, rby = (-1.f - oy) / vy;
    float raz = (1.f - oz) / vz, rbz = (-1.f - oz) / vz;
    float tmn = fmaxf(fmaxf(fminf(rax, rbx), fminf(ray_, rby)), fminf(raz, rbz));
    float tmx = fminf(fminf(fmaxf(rax, rbx), fmaxf(ray_, rby)), fmaxf(raz, rbz));
    tmn = fminf(fmaxf(tmn, NEARC), FARC);
    tmx = fminf(fmaxf(tmx, NEARC), FARC);
    float mask = (tmx <= tmn) ? 1.f : 0.f;
    float nn = sqrtf(dx*dx + dy*dy + dz*dz);
    g_rayinfo[4*r+0] = tmn;
    g_rayinfo[4*r+1] = nn;
    g_rayinfo[4*r+2] = mask;
    g_rayinfo[4*r+3] = 0.f;

    // positional encoding of viewdir (per-ray constant) folded into dir bias
    float wx = vd[3*r], wy = vd[3*r+1], wz = vd[3*r+2];
    float emb[39];
    emb[0] = wx; emb[1] = wy; emb[2] = wz;
    float f = 1.f;
#pragma unroll
    for (int l = 0; l < 6; l++) {
        emb[3+6*l+0] = sinf(wx*f); emb[3+6*l+1] = sinf(wy*f); emb[3+6*l+2] = sinf(wz*f);
        emb[3+6*l+3] = cosf(wx*f); emb[3+6*l+4] = cosf(wy*f); emb[3+6*l+5] = cosf(wz*f);
        f *= 2.f;
    }
#pragma unroll
    for (int j = 0; j < 16; j++) {
        float acc = db1[j];
#pragma unroll
        for (int k = 0; k < 39; k++) acc += emb[k] * dw1[(15+k)*16 + j];
        g_dbias[16*r + j] = acc;
    }
}

// =====================================================================
// Kernel 2: per-sample MLP evaluation -> scratch {alpha, rgb}
// one block per ray; 256 threads loop over 3 sample chunks
// =====================================================================
// shared weight offsets (floats) — all even, rows 16B-aligned
#define O_AW1 0
#define O_AB1 480
#define O_AW2 512
#define O_AB2 1536
#define O_AW3 1568
#define O_AB3 1696
#define O_PW1 1700
#define O_PB1 1892
#define O_PW2 1908
#define O_PB2 2164
#define O_PW3 2180
#define O_PB3 2436
#define O_DW1 2452
#define O_DW2 2692
#define O_DB2 2948
#define O_DW3 2964
#define O_DB3 3220
#define O_DW4 3236
#define O_DB4 3284
#define SW_TOT 3288

// packed layer: IN scalar inputs -> OUT (=2*OUTH) packed accumulators
template<int IN, int OUTH>
__device__ __forceinline__ void layer2(const float* __restrict__ x,
                                       const float* __restrict__ sw_w,
                                       const float* __restrict__ sw_b,
                                       u64* acc) {
    const u64* b2 = reinterpret_cast<const u64*>(sw_b);
#pragma unroll
    for (int j = 0; j < OUTH; j++) acc[j] = b2[j];
#pragma unroll
    for (int i = 0; i < IN; i++) {
        u64 xb = pk2(x[i], x[i]);
        const ulonglong2* w = reinterpret_cast<const ulonglong2*>(sw_w + i * (2*OUTH));
#pragma unroll
        for (int j = 0; j < OUTH/2; j++) {
            ulonglong2 ww = w[j];
            fma2(acc[2*j+0], xb, ww.x);
            fma2(acc[2*j+1], xb, ww.y);
        }
    }
}

template<int OUTH>
__device__ __forceinline__ void relu_unpack(const u64* acc, float* out) {
#pragma unroll
    for (int j = 0; j < OUTH; j++) {
        float a, b; upk2(acc[j], a, b);
        out[2*j]   = fmaxf(a, 0.f);
        out[2*j+1] = fmaxf(b, 0.f);
    }
}

__global__ __launch_bounds__(256) void k_phaseA(
    const float* __restrict__ ro, const float* __restrict__ rd,
    const float* __restrict__ aw1, const float* __restrict__ ab1,
    const float* __restrict__ aw2, const float* __restrict__ ab2,
    const float* __restrict__ aw3, const float* __restrict__ ab3,
    const float* __restrict__ pw1, const float* __restrict__ pb1,
    const float* __restrict__ pw2, const float* __restrict__ pb2,
    const float* __restrict__ pw3, const float* __restrict__ pb3,
    const float* __restrict__ dw1,
    const float* __restrict__ dw2, const float* __restrict__ db2,
    const float* __restrict__ dw3, const float* __restrict__ db3,
    const float* __restrict__ dw4, const float* __restrict__ db4)
{
    __shared__ __align__(16) float sw[SW_TOT];
    __shared__ __align__(16) float s_db[16];
    __shared__ float s_ray[9];   // tmin, |d|, mask, ox,oy,oz, dx,dy,dz
    {
        int t = threadIdx.x;
        for (int i = t; i < 480;  i += 256) sw[O_AW1 + i] = aw1[i];
        for (int i = t; i < 32;   i += 256) sw[O_AB1 + i] = ab1[i];
        for (int i = t; i < 1024; i += 256) sw[O_AW2 + i] = aw2[i];
        for (int i = t; i < 32;   i += 256) sw[O_AB2 + i] = ab2[i];
        for (int i = t; i < 128;  i += 256) sw[O_AW3 + i] = aw3[i];
        for (int i = t; i < 4;    i += 256) sw[O_AB3 + i] = ab3[i];
        for (int i = t; i < 192;  i += 256) sw[O_PW1 + i] = pw1[i];
        for (int i = t; i < 16;   i += 256) sw[O_PB1 + i] = pb1[i];
        for (int i = t; i < 256;  i += 256) sw[O_PW2 + i] = pw2[i];
        for (int i = t; i < 16;   i += 256) sw[O_PB2 + i] = pb2[i];
        for (int i = t; i < 256;  i += 256) sw[O_PW3 + i] = pw3[i];
        for (int i = t; i < 16;   i += 256) sw[O_PB3 + i] = pb3[i];
        for (int i = t; i < 240;  i += 256) sw[O_DW1 + i] = dw1[i];  // rows 0..14 only
        for (int i = t; i < 256;  i += 256) sw[O_DW2 + i] = dw2[i];
        for (int i = t; i < 16;   i += 256) sw[O_DB2 + i] = db2[i];
        for (int i = t; i < 256;  i += 256) sw[O_DW3 + i] = dw3[i];
        for (int i = t; i < 16;   i += 256) sw[O_DB3 + i] = db3[i];
        for (int i = t; i < 48;   i += 256) sw[O_DW4 + i] = dw4[i];
        for (int i = t; i < 3;    i += 256) sw[O_DB4 + i] = db4[i];
        int ray0 = blockIdx.x;
        if (t < 16) s_db[t] = g_dbias[16*ray0 + t];
        if (t < 3)  s_ray[t] = g_rayinfo[4*ray0 + t];
        if (t >= 3 && t < 6) s_ray[t] = ro[3*ray0 + (t-3)];
        if (t >= 6 && t < 9) s_ray[t] = rd[3*ray0 + (t-6)];
    }
    __syncthreads();

    int ray = blockIdx.x;
    float tmn = s_ray[0], rn = s_ray[1], mask = s_ray[2];
    float rinv = STEPW / rn;
    float ox = s_ray[3], oy = s_ray[4], oz = s_ray[5];
    float ddx = s_ray[6], ddy = s_ray[7], ddz = s_ray[8];

    for (int s = threadIdx.x; s < NS; s += 256) {
        int oi = ray * NS + s;
        float it = tmn + rinv * (float)s;
        float px = ox + ddx * it;
        float py = oy + ddy * it;
        float pz = oz + ddz * it;
        bool inb = (mask == 0.f) &&
                   px >= -1.f && px <= 1.f &&
                   py >= -1.f && py <= 1.f &&
                   pz >= -1.f && pz <= 1.f;
        if (!inb) { g_scratch[oi] = make_float4(0.f, 0.f, 0.f, 0.f); continue; }

        // ---- trilinear from channel-last grid (packed accumulators) ----
        float gx = (px + 1.f) * 0.5f * 159.f;
        float gy = (py + 1.f) * 0.5f * 159.f;
        float gz = (pz + 1.f) * 0.5f * 159.f;
        float fx0 = floorf(gx), fy0 = floorf(gy), fz0 = floorf(gz);
        float wx1 = gx - fx0, wy1 = gy - fy0, wz1 = gz - fz0;
        float wx0 = 1.f - wx1, wy0 = 1.f - wy1, wz0 = 1.f - wz1;
        int ix0 = min(max((int)fx0, 0), 159); int ix1 = min(ix0 + 1, 159);
        int iy0 = min(max((int)fy0, 0), 159); int iy1 = min(iy0 + 1, 159);
        int iz0 = min(max((int)fz0, 0), 159); int iz1 = min(iz0 + 1, 159);

        u64 lat2[6];
#pragma unroll
        for (int k = 0; k < 6; k++) lat2[k] = 0ull;

#define ADD_CORNER(X, Y, Z, W) {                                                     \
            const ulonglong2* gp = reinterpret_cast<const ulonglong2*>(              \
                g_grid_t + (size_t)((((X)*160 + (Y))*160) + (Z)) * 12);              \
            ulonglong2 A = __ldg(gp), B = __ldg(gp+1), C = __ldg(gp+2);              \
            float W_ = (W);                                                          \
            u64 wb = pk2(W_, W_);                                                    \
            fma2(lat2[0], wb, A.x); fma2(lat2[1], wb, A.y);                          \
            fma2(lat2[2], wb, B.x); fma2(lat2[3], wb, B.y);                          \
            fma2(lat2[4], wb, C.x); fma2(lat2[5], wb, C.y); }

        ADD_CORNER(ix0, iy0, iz0, wx0*wy0*wz0);
        ADD_CORNER(ix0, iy0, iz1, wx0*wy0*wz1);
        ADD_CORNER(ix0, iy1, iz0, wx0*wy1*wz0);
        ADD_CORNER(ix0, iy1, iz1, wx0*wy1*wz1);
        ADD_CORNER(ix1, iy0, iz0, wx1*wy0*wz0);
        ADD_CORNER(ix1, iy0, iz1, wx1*wy0*wz1);
        ADD_CORNER(ix1, iy1, iz0, wx1*wy1*wz0);
        ADD_CORNER(ix1, iy1, iz1, wx1*wy1*wz1);
#undef ADD_CORNER

        float lat[12];
#pragma unroll
        for (int k = 0; k < 6; k++) upk2(lat2[k], lat[2*k], lat[2*k+1]);

        // ---- attention MLP: [pz,py,px, lat] (15) -> 32 -> 32 -> 4 -> softmax[1]
        float xin[15];
        xin[0] = pz; xin[1] = py; xin[2] = px;
#pragma unroll
        for (int k = 0; k < 12; k++) xin[3+k] = lat[k];

        u64 acc16[16];
        float h1[32], h2[32];
        layer2<15, 16>(xin, &sw[O_AW1], &sw[O_AB1], acc16);
        relu_unpack<16>(acc16, h1);
        layer2<32, 16>(h1, &sw[O_AW2], &sw[O_AB2], acc16);
        relu_unpack<16>(acc16, h2);

        u64 accO[2];
        layer2<32, 2>(h2, &sw[O_AW3], &sw[O_AB3], accO);
        float o0, o1, o2, o3;
        upk2(accO[0], o0, o1); upk2(accO[1], o2, o3);
        float mx = fmaxf(fmaxf(o0, o1), fmaxf(o2, o3));
        float e0 = expf(o0-mx), e1 = expf(o1-mx), e2 = expf(o2-mx), e3 = expf(o3-mx);
        float att1 = e1 / (e0 + e1 + e2 + e3);

        // ---- pos MLP: lat (12) -> 16 -> 16 -> 16 ----
        u64 acc8[8];
        float p1[16], p2[16], p3[16];
        layer2<12, 8>(lat, &sw[O_PW1], &sw[O_PB1], acc8);
        relu_unpack<8>(acc8, p1);
        layer2<16, 8>(p1, &sw[O_PW2], &sw[O_PB2], acc8);
        relu_unpack<8>(acc8, p2);
        layer2<16, 8>(p2, &sw[O_PW3], &sw[O_PB3], acc8);
#pragma unroll
        for (int j = 0; j < 8; j++) upk2(acc8[j], p3[2*j], p3[2*j+1]);  // no relu

        // ---- dir MLP: [p3[1:16] ; emb(folded bias)] -> 16 -> 16 -> 16 -> 3 ----
        float d1[16], d2[16], d3[16];
        layer2<15, 8>(&p3[1], &sw[O_DW1], s_db, acc8);
        relu_unpack<8>(acc8, d1);
        layer2<16, 8>(d1, &sw[O_DW2], &sw[O_DB2], acc8);
        relu_unpack<8>(acc8, d2);
        layer2<16, 8>(d2, &sw[O_DW3], &sw[O_DB3], acc8);
        relu_unpack<8>(acc8, d3);

        float r0 = sw[O_DB4+0], r1 = sw[O_DB4+1], r2 = sw[O_DB4+2];
#pragma unroll
        for (int i = 0; i < 16; i++) {
            float xi = d3[i];
            r0 += xi * sw[O_DW4 + i*3 + 0];
            r1 += xi * sw[O_DW4 + i*3 + 1];
            r2 += xi * sw[O_DW4 + i*3 + 2];
        }

        // ---- activations ----
        float dens = att1 * p3[0];
        float xs = dens + ACT_SHIFT;
        float sp = fmaxf(xs, 0.f) + log1pf(expf(-fabsf(xs)));   // softplus
        float alpha = 1.f - expf(-sp * 0.5f);
        float c0 = 1.f / (1.f + expf(-att1 * r0));
        float c1 = 1.f / (1.f + expf(-att1 * r1));
        float c2 = 1.f / (1.f + expf(-att1 * r2));

        g_scratch[oi] = make_float4(alpha, c0, c1, c2);
    }
}

// =====================================================================
// Kernel 3: warp-per-ray alpha compositing (shfl prefix-product scan)
// =====================================================================
__global__ __launch_bounds__(256) void k_phaseB(float* __restrict__ out) {
    int gid  = blockIdx.x * blockDim.x + threadIdx.x;
    int ray  = gid >> 5;
    int lane = gid & 31;
    if (ray >= NRAY) return;

    float tmn = g_rayinfo[4*ray], rn = g_rayinfo[4*ray+1];
    float base_depth = tmn * rn;

    float T = 1.f;
    float sr = 0.f, sg = 0.f, sb = 0.f, sd = 0.f, sa = 0.f;

    for (int c0 = 0; c0 < NS; c0 += 32) {
        int s = c0 + lane;
        float4 rec = make_float4(0.f, 0.f, 0.f, 0.f);
        if (s < NS) rec = g_scratch[ray*NS + s];
        float a = rec.x;
        float q = fmaxf(1.f - a, 1e-10f);
        float ip = q;
#pragma unroll
        for (int off = 1; off < 32; off <<= 1) {
            float v = __shfl_up_sync(0xFFFFFFFFu, ip, off);
            if (lane >= off) ip *= v;
        }
        float ep = __shfl_up_sync(0xFFFFFFFFu, ip, 1);
        if (lane == 0) ep = 1.f;
        float w = a * T * ep;
        sr += w * rec.y;
        sg += w * rec.z;
        sb += w * rec.w;
        sd += w * (base_depth + STEPW * (float)s);
        sa += w;
        T *= __shfl_sync(0xFFFFFFFFu, ip, 31);
    }

#pragma unroll
    for (int off = 16; off > 0; off >>= 1) {
        sr += __shfl_xor_sync(0xFFFFFFFFu, sr, off);
        sg += __shfl_xor_sync(0xFFFFFFFFu, sg, off);
        sb += __shfl_xor_sync(0xFFFFFFFFu, sb, off);
        sd += __shfl_xor_sync(0xFFFFFFFFu, sd, off);
        sa += __shfl_xor_sync(0xFFFFFFFFu, sa, off);
    }

    if (lane == 0) {
        float depth = sd + T * FARC;
        out[ray*6+0] = sr + T * BGC;
        out[ray*6+1] = sg + T * BGC;
        out[ray*6+2] = sb + T * BGC;
        out[ray*6+3] = depth;
        out[ray*6+4] = 1.f / depth;
        out[ray*6+5] = sa;
    }
}

// =====================================================================
extern "C" void kernel_launch(void* const* d_in, const int* in_sizes, int n_in,
                              void* d_out, int out_size) {
    const float* ro  = (const float*)d_in[0];
    const float* rd  = (const float*)d_in[1];
    const float* vd  = (const float*)d_in[2];
    const float* grd = (const float*)d_in[3];
    const float* aw1 = (const float*)d_in[4];
    const float* ab1 = (const float*)d_in[5];
    const float* aw2 = (const float*)d_in[6];
    const float* ab2 = (const float*)d_in[7];
    const float* aw3 = (const float*)d_in[8];
    const float* ab3 = (const float*)d_in[9];
    const float* pw1 = (const float*)d_in[10];
    const float* pb1 = (const float*)d_in[11];
    const float* pw2 = (const float*)d_in[12];
    const float* pb2 = (const float*)d_in[13];
    const float* pw3 = (const float*)d_in[14];
    const float* pb3 = (const float*)d_in[15];
    const float* dw1 = (const float*)d_in[16];
    const float* db1 = (const float*)d_in[17];
    const float* dw2 = (const float*)d_in[18];
    const float* db2 = (const float*)d_in[19];
    const float* dw3 = (const float*)d_in[20];
    const float* db3 = (const float*)d_in[21];
    const float* dw4 = (const float*)d_in[22];
    const float* db4 = (const float*)d_in[23];

    k_transpose<<<(R3 + 255) / 256, 256>>>(grd);
    k_raypre<<<(NRAY + 255) / 256, 256>>>(ro, rd, vd, dw1, db1);
    k_phaseA<<<NRAY, 256>>>(ro, rd,
                            aw1, ab1, aw2, ab2, aw3, ab3,
                            pw1, pb1, pw2, pb2, pw3, pb3,
                            dw1, dw2, db2, dw3, db3, dw4, db4);
    k_phaseB<<<(NRAY * 32) / 256, 256>>>((float*)d_out);
}